// round 11
// baseline (speedup 1.0000x reference)
#include <cuda_runtime.h>
#include <cuda_fp16.h>
#include <stdint.h>

#define BATCH   2
#define SEQ     2048
#define DMODEL  1024
#define NHEADS  16
#define DK      64
#define MROWS   (BATCH * SEQ)                      // 4096
#define OUT_ELEMS ((size_t)MROWS * DMODEL)

typedef __half fp16;

// ---------------- scratch (device globals) ----------------
__device__ static fp16 g_qxh[MROWS * DMODEL], g_qxl[MROWS * DMODEL];
__device__ static fp16 g_kxh[MROWS * DMODEL], g_kxl[MROWS * DMODEL];
__device__ static fp16 g_vx [MROWS * DMODEL];
__device__ static fp16 g_wq[DMODEL * DMODEL], g_wk[DMODEL * DMODEL];
__device__ static fp16 g_wv[DMODEL * DMODEL], g_wo[DMODEL * DMODEL];
__device__ static fp16 g_qh[MROWS * DMODEL], g_ql[MROWS * DMODEL];   // q split [b][h][s][d]
__device__ static fp16 g_k [MROWS * DMODEL];                         // k single [b][h][s][d]
__device__ static fp16 g_v [MROWS * DMODEL];                         // v single [b][h][d][s]
__device__ static fp16 g_ao[MROWS * DMODEL];                         // single fp16
__device__ static float g_linv[BATCH * NHEADS * SEQ];

// ---------------- helpers ----------------
__device__ __forceinline__ uint32_t sptr(const void* p) {
    return (uint32_t)__cvta_generic_to_shared(p);
}
__device__ __forceinline__ void ldsm4(uint32_t& r0, uint32_t& r1, uint32_t& r2,
                                      uint32_t& r3, uint32_t a) {
    asm volatile("ldmatrix.sync.aligned.m8n8.x4.shared.b16 {%0,%1,%2,%3},[%4];"
                 : "=r"(r0), "=r"(r1), "=r"(r2), "=r"(r3) : "r"(a));
}
__device__ __forceinline__ void mma_f16(float c[4], const uint32_t a[4],
                                        uint32_t b0, uint32_t b1) {
    asm volatile(
        "mma.sync.aligned.m16n8k16.row.col.f32.f16.f16.f32 "
        "{%0,%1,%2,%3},{%4,%5,%6,%7},{%8,%9},{%0,%1,%2,%3};"
        : "+f"(c[0]), "+f"(c[1]), "+f"(c[2]), "+f"(c[3])
        : "r"(a[0]), "r"(a[1]), "r"(a[2]), "r"(a[3]), "r"(b0), "r"(b1));
}
__device__ __forceinline__ void split2(float x, fp16& h, fp16& l) {
    h = __float2half_rn(x);
    l = __float2half_rn(x - __half2float(h));
}
__device__ __forceinline__ uint32_t pack2(fp16 a, fp16 b) {
    __half2 t; t.x = a; t.y = b;
    return *(uint32_t*)&t;
}
__device__ __forceinline__ void cpa16(void* dst, const void* src) {
    asm volatile("cp.async.cg.shared.global [%0],[%1],16;"
                 :: "r"(sptr(dst)), "l"(__cvta_generic_to_global(src)));
}
#define CP_COMMIT  asm volatile("cp.async.commit_group;")
#define CP_WAIT0   asm volatile("cp.async.wait_group 0;")
#define CP_WAIT1   asm volatile("cp.async.wait_group 1;")

// ---------------- split / convert kernels ----------------
__global__ __launch_bounds__(256)
void split_kernel(const float* __restrict__ in, fp16* __restrict__ oh,
                  fp16* __restrict__ ol, int n4)
{
    int i = blockIdx.x * blockDim.x + threadIdx.x;
    if (i >= n4) return;
    float4 v = ((const float4*)in)[i];
    fp16 h0, l0, h1, l1, h2, l2, h3, l3;
    split2(v.x, h0, l0); split2(v.y, h1, l1);
    split2(v.z, h2, l2); split2(v.w, h3, l3);
    ((uint2*)oh)[i] = make_uint2(pack2(h0, h1), pack2(h2, h3));
    ((uint2*)ol)[i] = make_uint2(pack2(l0, l1), pack2(l2, l3));
}
__global__ __launch_bounds__(256)
void cvt_kernel(const float* __restrict__ in, fp16* __restrict__ o, int n4)
{
    int i = blockIdx.x * blockDim.x + threadIdx.x;
    if (i >= n4) return;
    float4 v = ((const float4*)in)[i];
    ((uint2*)o)[i] = make_uint2(pack2(__float2half_rn(v.x), __float2half_rn(v.y)),
                                pack2(__float2half_rn(v.z), __float2half_rn(v.w)));
}
// fused 4-weight convert (blockIdx.y selects weight)
__global__ __launch_bounds__(256)
void cvt4_kernel(const float* __restrict__ w0, const float* __restrict__ w1,
                 const float* __restrict__ w2, const float* __restrict__ w3,
                 fp16* __restrict__ o0, fp16* __restrict__ o1,
                 fp16* __restrict__ o2, fp16* __restrict__ o3, int n4)
{
    int i = blockIdx.x * blockDim.x + threadIdx.x;
    if (i >= n4) return;
    int z = blockIdx.y;
    const float* in = (z == 0) ? w0 : (z == 1) ? w1 : (z == 2) ? w2 : w3;
    fp16* o = (z == 0) ? o0 : (z == 1) ? o1 : (z == 2) ? o2 : o3;
    float4 v = ((const float4*)in)[i];
    ((uint2*)o)[i] = make_uint2(pack2(__float2half_rn(v.x), __float2half_rn(v.y)),
                                pack2(__float2half_rn(v.z), __float2half_rn(v.w)));
}

// ---------------------------------------------------------------------------
// GEMM mainloops: 128x128x32, 8 warps (2x4), 3-stage cp.async pipeline.
// MAINLOOP2: split-A x single-B (2 mma); MAINLOOP1: single-A x single-B (1 mma)
// ---------------------------------------------------------------------------
#define G_LDS 40
#define G_TILE (128 * G_LDS)
#define SMEM_G2_BYTES (9 * G_TILE * 2)     // 92160 (3 stages x 3 tiles)
#define SMEM_G1_BYTES (6 * G_TILE * 2)     // 61440 (3 stages x 2 tiles)

#define GEMM_WAIT(kk, NK)                                                    \
    if ((kk) + 1 < (NK)) { CP_WAIT1; } else { CP_WAIT0; }                    \
    __syncthreads();

#define GEMM_MAINLOOP2(Ah, Al, Bw)                                           \
    float acc[4][4][4];                                                      \
    _Pragma("unroll")                                                        \
    for (int i = 0; i < 4; ++i)                                              \
        _Pragma("unroll")                                                    \
        for (int j = 0; j < 4; ++j)                                          \
            _Pragma("unroll")                                                \
            for (int e = 0; e < 4; ++e) acc[i][j][e] = 0.f;                  \
    auto issue = [&](int kk) {                                               \
        fp16* d = smg + (kk % 3) * 3 * G_TILE;                               \
        const fp16* srcs[3] = {                                              \
            Ah + (size_t)m0 * DMODEL + kk * 32,                              \
            Al + (size_t)m0 * DMODEL + kk * 32,                              \
            Bw + (size_t)n0 * DMODEL + kk * 32};                             \
        const int r = t >> 2, o = (t & 3) * 8;                               \
        _Pragma("unroll")                                                    \
        for (int tl = 0; tl < 3; ++tl) {                                     \
            cpa16(d + tl * G_TILE + r * G_LDS + o,                           \
                  srcs[tl] + (size_t)r * DMODEL + o);                        \
            cpa16(d + tl * G_TILE + (r + 64) * G_LDS + o,                    \
                  srcs[tl] + (size_t)(r + 64) * DMODEL + o);                 \
        }                                                                    \
    };                                                                       \
    const int NK = DMODEL / 32;                                              \
    issue(0); CP_COMMIT;                                                     \
    issue(1); CP_COMMIT;                                                     \
    for (int kk = 0; kk < NK; ++kk) {                                        \
        GEMM_WAIT(kk, NK)                                                    \
        if (kk + 2 < NK) { issue(kk + 2); CP_COMMIT; }                       \
        const fp16* sAh = smg + (kk % 3) * 3 * G_TILE;                       \
        const fp16* sAl = sAh + G_TILE;                                      \
        const fp16* sB  = sAl + G_TILE;                                      \
        _Pragma("unroll")                                                    \
        for (int k16 = 0; k16 < 32; k16 += 16) {                             \
            uint32_t ah[4][4], al[4][4], bh[4][2];                           \
            _Pragma("unroll")                                                \
            for (int mt = 0; mt < 4; ++mt) {                                 \
                int row = wm * 64 + mt * 16 + lr + 8 * (lm & 1);             \
                int col = k16 + 8 * (lm >> 1);                               \
                ldsm4(ah[mt][0], ah[mt][1], ah[mt][2], ah[mt][3],            \
                      sptr(&sAh[row * G_LDS + col]));                        \
                ldsm4(al[mt][0], al[mt][1], al[mt][2], al[mt][3],            \
                      sptr(&sAl[row * G_LDS + col]));                        \
            }                                                                \
            _Pragma("unroll")                                                \
            for (int g = 0; g < 2; ++g) {                                    \
                int row = wn * 32 + g * 16 + 8 * (lm >> 1) + lr;             \
                int col = k16 + 8 * (lm & 1);                                \
                ldsm4(bh[2 * g][0], bh[2 * g][1], bh[2 * g + 1][0],          \
                      bh[2 * g + 1][1], sptr(&sB[row * G_LDS + col]));       \
            }                                                                \
            _Pragma("unroll")                                                \
            for (int mt = 0; mt < 4; ++mt)                                   \
                _Pragma("unroll")                                            \
                for (int nt = 0; nt < 4; ++nt) {                             \
                    mma_f16(acc[mt][nt], ah[mt], bh[nt][0], bh[nt][1]);      \
                    mma_f16(acc[mt][nt], al[mt], bh[nt][0], bh[nt][1]);      \
                }                                                            \
        }                                                                    \
    }

#define GEMM_MAINLOOP1(Aa, Bw)                                               \
    float acc[4][4][4];                                                      \
    _Pragma("unroll")                                                        \
    for (int i = 0; i < 4; ++i)                                              \
        _Pragma("unroll")                                                    \
        for (int j = 0; j < 4; ++j)                                          \
            _Pragma("unroll")                                                \
            for (int e = 0; e < 4; ++e) acc[i][j][e] = 0.f;                  \
    auto issue = [&](int kk) {                                               \
        fp16* d = smg + (kk % 3) * 2 * G_TILE;                               \
        const fp16* srcs[2] = {                                              \
            Aa + (size_t)m0 * DMODEL + kk * 32,                              \
            Bw + (size_t)n0 * DMODEL + kk * 32};                             \
        const int r = t >> 2, o = (t & 3) * 8;                               \
        _Pragma("unroll")                                                    \
        for (int tl = 0; tl < 2; ++tl) {                                     \
            cpa16(d + tl * G_TILE + r * G_LDS + o,                           \
                  srcs[tl] + (size_t)r * DMODEL + o);                        \
            cpa16(d + tl * G_TILE + (r + 64) * G_LDS + o,                    \
                  srcs[tl] + (size_t)(r + 64) * DMODEL + o);                 \
        }                                                                    \
    };                                                                       \
    const int NK = DMODEL / 32;                                              \
    issue(0); CP_COMMIT;                                                     \
    issue(1); CP_COMMIT;                                                     \
    for (int kk = 0; kk < NK; ++kk) {                                        \
        GEMM_WAIT(kk, NK)                                                    \
        if (kk + 2 < NK) { issue(kk + 2); CP_COMMIT; }                       \
        const fp16* sA = smg + (kk % 3) * 2 * G_TILE;                        \
        const fp16* sB = sA + G_TILE;                                        \
        _Pragma("unroll")                                                    \
        for (int k16 = 0; k16 < 32; k16 += 16) {                             \
            uint32_t ah[4][4], bh[4][2];                                     \
            _Pragma("unroll")                                                \
            for (int mt = 0; mt < 4; ++mt) {                                 \
                int row = wm * 64 + mt * 16 + lr + 8 * (lm & 1);             \
                int col = k16 + 8 * (lm >> 1);                               \
                ldsm4(ah[mt][0], ah[mt][1], ah[mt][2], ah[mt][3],            \
                      sptr(&sA[row * G_LDS + col]));                         \
            }                                                                \
            _Pragma("unroll")                                                \
            for (int g = 0; g < 2; ++g) {                                    \
                int row = wn * 32 + g * 16 + 8 * (lm >> 1) + lr;             \
                int col = k16 + 8 * (lm & 1);                                \
                ldsm4(bh[2 * g][0], bh[2 * g][1], bh[2 * g + 1][0],          \
                      bh[2 * g + 1][1], sptr(&sB[row * G_LDS + col]));       \
            }                                                                \
            _Pragma("unroll")                                                \
            for (int mt = 0; mt < 4; ++mt)                                   \
                _Pragma("unroll")                                            \
                for (int nt = 0; nt < 4; ++nt)                               \
                    mma_f16(acc[mt][nt], ah[mt], bh[nt][0], bh[nt][1]);      \
        }                                                                    \
    }

// Fused QKV projection: z = 0 (Q, split-A split-out), 1 (K, split-A single-out),
// 2 (V, single-A transposed single-out)
__global__ __launch_bounds__(256)
void gemm_qkv(const fp16* __restrict__ qxh, const fp16* __restrict__ qxl,
              const fp16* __restrict__ kxh, const fp16* __restrict__ kxl,
              const fp16* __restrict__ vx,
              const fp16* __restrict__ wq, const fp16* __restrict__ wk,
              const fp16* __restrict__ wv,
              fp16* __restrict__ qh, fp16* __restrict__ ql,
              fp16* __restrict__ kkp, fp16* __restrict__ vvp)
{
    extern __shared__ fp16 smg[];
    const int t = threadIdx.x;
    const int m0 = blockIdx.y * 128, n0 = blockIdx.x * 128;
    const int z = blockIdx.z;
    const int w = t >> 5, lane = t & 31;
    const int wm = w >> 2, wn = w & 3;
    const int lm = lane >> 3, lr = lane & 7;
    const int cr = lane >> 2, cc = lane & 3;

    if (z == 2) {
        GEMM_MAINLOOP1(vx, wv)
#pragma unroll
        for (int mt = 0; mt < 4; ++mt)
#pragma unroll
            for (int nt = 0; nt < 4; ++nt)
#pragma unroll
                for (int half = 0; half < 2; ++half) {
                    int gm = m0 + wm * 64 + mt * 16 + cr + 8 * half;
                    int gn = n0 + wn * 32 + nt * 8 + 2 * cc;
                    int b = gm >> 11, s = gm & 2047, h = gn >> 6, d = gn & 63;
                    size_t idx = (((size_t)(b * NHEADS + h) * DK) + d) * SEQ + s;
                    vvp[idx]       = __float2half_rn(acc[mt][nt][2 * half + 0]);
                    vvp[idx + SEQ] = __float2half_rn(acc[mt][nt][2 * half + 1]);
                }
    } else {
        const fp16* Ah = (z == 0) ? qxh : kxh;
        const fp16* Al = (z == 0) ? qxl : kxl;
        const fp16* Bw = (z == 0) ? wq  : wk;
        GEMM_MAINLOOP2(Ah, Al, Bw)
#pragma unroll
        for (int mt = 0; mt < 4; ++mt)
#pragma unroll
            for (int nt = 0; nt < 4; ++nt)
#pragma unroll
                for (int half = 0; half < 2; ++half) {
                    int gm = m0 + wm * 64 + mt * 16 + cr + 8 * half;
                    int gn = n0 + wn * 32 + nt * 8 + 2 * cc;
                    float v0 = acc[mt][nt][2 * half + 0];
                    float v1 = acc[mt][nt][2 * half + 1];
                    int b = gm >> 11, s = gm & 2047, h = gn >> 6, d = gn & 63;
                    size_t idx = (((size_t)(b * NHEADS + h) * SEQ) + s) * DK + d;
                    if (z == 0) {
                        fp16 h0, l0, h1, l1;
                        split2(v0, h0, l0); split2(v1, h1, l1);
                        *(uint32_t*)(qh + idx) = pack2(h0, h1);
                        *(uint32_t*)(ql + idx) = pack2(l0, l1);
                    } else {
                        *(uint32_t*)(kkp + idx) =
                            pack2(__float2half_rn(v0), __float2half_rn(v1));
                    }
                }
    }
}

// Output projection: single-A (ao fp16) x single-B, fp32 + bias
__global__ __launch_bounds__(256)
void gemm_out(const fp16* __restrict__ ao, const fp16* __restrict__ wo,
              float* __restrict__ Cout, const float* __restrict__ bias)
{
    extern __shared__ fp16 smg[];
    const int t = threadIdx.x;
    const int m0 = blockIdx.y * 128, n0 = blockIdx.x * 128;
    const int w = t >> 5, lane = t & 31;
    const int wm = w >> 2, wn = w & 3;
    const int lm = lane >> 3, lr = lane & 7;
    const int cr = lane >> 2, cc = lane & 3;

    GEMM_MAINLOOP1(ao, wo)

#pragma unroll
    for (int mt = 0; mt < 4; ++mt)
#pragma unroll
        for (int nt = 0; nt < 4; ++nt)
#pragma unroll
            for (int half = 0; half < 2; ++half) {
                int gm = m0 + wm * 64 + mt * 16 + cr + 8 * half;
                int gn = n0 + wn * 32 + nt * 8 + 2 * cc;
                *(float2*)(Cout + (size_t)gm * DMODEL + gn) =
                    make_float2(acc[mt][nt][2 * half + 0] + bias[gn],
                                acc[mt][nt][2 * half + 1] + bias[gn + 1]);
            }
}

// ---------------------------------------------------------------------------
// Single-pass attention, 128-row Q tiles, single-fp16 P in PV, ao single out.
// ---------------------------------------------------------------------------
#define A_LDS 72
#define SMEM_ATTN_BYTES ((2 * 128 + 4 * 64) * A_LDS * 2)    // 73728

__global__ __launch_bounds__(256, 2)
void attn_1p(const fp16* __restrict__ qh, const fp16* __restrict__ ql,
             const fp16* __restrict__ kk_g, const fp16* __restrict__ vv_g,
             float* __restrict__ attn, fp16* __restrict__ ao,
             float* __restrict__ linv_g, int write_attn)
{
    extern __shared__ fp16 sma[];
    fp16* Qh = sma;
    fp16* Ql = sma + 128 * A_LDS;
    fp16* KB[2] = {sma + 256 * A_LDS, sma + 320 * A_LDS};
    fp16* VB[2] = {sma + 384 * A_LDS, sma + 448 * A_LDS};

    const int qt = (int)gridDim.x - 1 - (int)blockIdx.x;   // heavy first
    const int h = blockIdx.y, b = blockIdx.z;
    const int q0 = qt * 128;
    const int t = threadIdx.x, wm = t >> 5, lane = t & 31;
    const int lm = lane >> 3, lr = lane & 7;
    const int cr = lane >> 2, cc = lane & 3;
    const float scale = 0.125f;

    const size_t bh = (size_t)(b * NHEADS + h);
    const fp16* qbh = qh + bh * SEQ * DK;
    const fp16* qbl = ql + bh * SEQ * DK;
    const fp16* kb  = kk_g + bh * SEQ * DK;
    const fp16* vb  = vv_g + bh * DK * SEQ;

    auto cpa_kv = [&](fp16* dst, const fp16* src, int rstride) {
        const int r = t >> 2, o = (t & 3) * 16;
        cpa16(dst + r * A_LDS + o,     src + (size_t)r * rstride + o);
        cpa16(dst + r * A_LDS + o + 8, src + (size_t)r * rstride + o + 8);
    };
    auto cpa_q = [&](fp16* dst, const fp16* src) {
        const int r = t >> 1, o = (t & 1) * 32;
#pragma unroll
        for (int u = 0; u < 32; u += 8)
            cpa16(dst + r * A_LDS + o + u, src + (size_t)r * DK + o + u);
    };

    cpa_q(Qh, qbh + (size_t)q0 * DK);
    cpa_q(Ql, qbl + (size_t)q0 * DK);
    cpa_kv(KB[0], kb, DK);
    cpa_kv(VB[0], vb, SEQ);
    CP_COMMIT;

    const int n_kt = 2 * qt + 2;
    float* attn_base = write_attn ? attn + (bh * SEQ + q0) * SEQ : (float*)0;
    if (write_attn) {   // zero fully-masked region j >= q0+128
        const int zr = t >> 1, zc = (t & 1) * 32;
        float4 z4 = make_float4(0.f, 0.f, 0.f, 0.f);
        for (int kt = n_kt; kt < SEQ / 64; ++kt) {
            float* dst = attn_base + (size_t)zr * SEQ + kt * 64 + zc;
#pragma unroll
            for (int u = 0; u < 32; u += 4) *(float4*)(dst + u) = z4;
        }
    }

    float o[8][4];
#pragma unroll
    for (int nt = 0; nt < 8; ++nt)
#pragma unroll
        for (int e = 0; e < 4; ++e) o[nt][e] = 0.f;
    float lp0 = 0.f, lp1 = 0.f;

    for (int kt = 0; kt < n_kt; ++kt) {
        CP_WAIT0;
        __syncthreads();
        if (kt + 1 < n_kt) {
            cpa_kv(KB[(kt + 1) & 1], kb + (size_t)(kt + 1) * 64 * DK, DK);
            cpa_kv(VB[(kt + 1) & 1], vb + (kt + 1) * 64, SEQ);
            CP_COMMIT;
        }
        const int k0 = kt * 64, buf = kt & 1;

        float s[8][4];
#pragma unroll
        for (int nt = 0; nt < 8; ++nt)
#pragma unroll
            for (int e = 0; e < 4; ++e) s[nt][e] = 0.f;
#pragma unroll
        for (int kc = 0; kc < 4; ++kc) {
            uint32_t af[4], alf[4];
            {
                int row = wm * 16 + lr + 8 * (lm & 1);
                int col = kc * 16 + 8 * (lm >> 1);
                ldsm4(af[0], af[1], af[2], af[3], sptr(&Qh[row * A_LDS + col]));
                ldsm4(alf[0], alf[1], alf[2], alf[3], sptr(&Ql[row * A_LDS + col]));
            }
#pragma unroll
            for (int g = 0; g < 4; ++g) {
                int row = g * 16 + 8 * (lm >> 1) + lr;
                int col = kc * 16 + 8 * (lm & 1);
                uint32_t b0, b1, b2, b3;
                ldsm4(b0, b1, b2, b3, sptr(&KB[buf][row * A_LDS + col]));
                mma_f16(s[2 * g],     af,  b0, b1);
                mma_f16(s[2 * g],     alf, b0, b1);
                mma_f16(s[2 * g + 1], af,  b2, b3);
                mma_f16(s[2 * g + 1], alf, b2, b3);
            }
        }

        uint32_t pp[4][4];
#pragma unroll
        for (int nt = 0; nt < 8; ++nt) {
#pragma unroll
            for (int half = 0; half < 2; ++half) {
                int i = wm * 16 + cr + 8 * half;
                int j = nt * 8 + 2 * cc;
                float p0 = 0.f, p1 = 0.f;
                if (k0 + j     <= q0 + i) p0 = __expf(s[nt][2 * half]     * scale);
                if (k0 + j + 1 <= q0 + i) p1 = __expf(s[nt][2 * half + 1] * scale);
                if (half) lp1 += p0 + p1; else lp0 += p0 + p1;
                if (write_attn)
                    *(float2*)(attn_base + (size_t)i * SEQ + k0 + j) = make_float2(p0, p1);
                pp[nt >> 1][(nt & 1) * 2 + half] =
                    pack2(__float2half_rn(p0), __float2half_rn(p1));
            }
        }

#pragma unroll
        for (int kc = 0; kc < 4; ++kc) {
#pragma unroll
            for (int g = 0; g < 4; ++g) {
                int row = g * 16 + 8 * (lm >> 1) + lr;
                int col = kc * 16 + 8 * (lm & 1);
                uint32_t b0, b1, b2, b3;
                ldsm4(b0, b1, b2, b3, sptr(&VB[buf][row * A_LDS + col]));
                mma_f16(o[2 * g],     pp[kc], b0, b1);
                mma_f16(o[2 * g + 1], pp[kc], b2, b3);
            }
        }
    }

    lp0 += __shfl_xor_sync(0xffffffff, lp0, 1);
    lp0 += __shfl_xor_sync(0xffffffff, lp0, 2);
    lp1 += __shfl_xor_sync(0xffffffff, lp1, 1);
    lp1 += __shfl_xor_sync(0xffffffff, lp1, 2);
    const float li0 = 1.0f / lp0;
    const float li1 = 1.0f / lp1;
    if (cc == 0) {
        linv_g[bh * SEQ + q0 + wm * 16 + cr]     = li0;
        linv_g[bh * SEQ + q0 + wm * 16 + cr + 8] = li1;
    }
#pragma unroll
    for (int nt = 0; nt < 8; ++nt)
#pragma unroll
        for (int half = 0; half < 2; ++half) {
            int i = wm * 16 + cr + 8 * half;
            int d = nt * 8 + 2 * cc;
            float li = half ? li1 : li0;
            size_t idx = (size_t)(b * SEQ + q0 + i) * DMODEL + h * DK + d;
            *(uint32_t*)(ao + idx) =
                pack2(__float2half_rn(o[nt][2 * half] * li),
                      __float2half_rn(o[nt][2 * half + 1] * li));
        }
}

// ---------------------------------------------------------------------------
// attn_norm: scale causal prefix of each attn row by 1/l.
// ---------------------------------------------------------------------------
__global__ __launch_bounds__(256)
void attn_norm(float* __restrict__ attn, const float* __restrict__ linv_g)
{
    const int qt = (int)gridDim.x - 1 - (int)blockIdx.x;
    const int h = blockIdx.y, b = blockIdx.z;
    const size_t bh = (size_t)(b * NHEADS + h);
    const int q0 = qt * 64;
    const int r = threadIdx.x >> 2, sub = threadIdx.x & 3;
    const float li = linv_g[bh * SEQ + q0 + r];
    float* row = attn + (bh * SEQ + q0 + r) * (size_t)SEQ;
    const int L = q0 + 64;
    for (int c = sub * 4; c < L; c += 16) {
        float4 v = *(float4*)(row + c);
        v.x *= li; v.y *= li; v.z *= li; v.w *= li;
        *(float4*)(row + c) = v;
    }
}

// ---------------------------------------------------------------------------
// Launch  (attn_1p is global launch index 5 -> ncu -s 5 captures it)
// ---------------------------------------------------------------------------
extern "C" void kernel_launch(void* const* d_in, const int* in_sizes, int n_in,
                              void* d_out, int out_size)
{
    const float* Q   = (const float*)d_in[0];
    const float* K   = (const float*)d_in[1];
    const float* V   = (const float*)d_in[2];
    const float* W_q = (const float*)d_in[3];
    const float* W_k = (const float*)d_in[4];
    const float* W_v = (const float*)d_in[5];
    const float* W_o = (const float*)d_in[6];
    const float* b_o = (const float*)d_in[7];
    float* out = (float*)d_out;

    const int write_attn = ((size_t)out_size > OUT_ELEMS) ? 1 : 0;
    float* attn = write_attn ? out + OUT_ELEMS : (float*)0;

    fp16 *qxh, *qxl, *kxh, *kxl, *vx;
    fp16 *wq, *wk, *wv, *wo;
    fp16 *qh, *ql, *kkp, *vvp, *ao;
    float* linv;
    cudaGetSymbolAddress((void**)&qxh, g_qxh); cudaGetSymbolAddress((void**)&qxl, g_qxl);
    cudaGetSymbolAddress((void**)&kxh, g_kxh); cudaGetSymbolAddress((void**)&kxl, g_kxl);
    cudaGetSymbolAddress((void**)&vx, g_vx);
    cudaGetSymbolAddress((void**)&wq, g_wq);   cudaGetSymbolAddress((void**)&wk, g_wk);
    cudaGetSymbolAddress((void**)&wv, g_wv);   cudaGetSymbolAddress((void**)&wo, g_wo);
    cudaGetSymbolAddress((void**)&qh, g_qh);   cudaGetSymbolAddress((void**)&ql, g_ql);
    cudaGetSymbolAddress((void**)&kkp, g_k);   cudaGetSymbolAddress((void**)&vvp, g_v);
    cudaGetSymbolAddress((void**)&ao, g_ao);
    cudaGetSymbolAddress((void**)&linv, g_linv);

    cudaFuncSetAttribute(gemm_qkv, cudaFuncAttributeMaxDynamicSharedMemorySize, SMEM_G2_BYTES);
    cudaFuncSetAttribute(gemm_out, cudaFuncAttributeMaxDynamicSharedMemorySize, SMEM_G1_BYTES);
    cudaFuncSetAttribute(attn_1p,  cudaFuncAttributeMaxDynamicSharedMemorySize, SMEM_ATTN_BYTES);

    const int n4x = MROWS * DMODEL / 4;
    const int n4w = DMODEL * DMODEL / 4;

    split_kernel<<<n4x / 256, 256>>>(Q, qxh, qxl, n4x);                    // 0
    split_kernel<<<n4x / 256, 256>>>(K, kxh, kxl, n4x);                    // 1
    cvt_kernel<<<n4x / 256, 256>>>(V, vx, n4x);                            // 2
    dim3 wgrid(n4w / 256, 4);
    cvt4_kernel<<<wgrid, 256>>>(W_q, W_k, W_v, W_o, wq, wk, wv, wo, n4w);  // 3

    dim3 qkvgrid(DMODEL / 128, MROWS / 128, 3);
    gemm_qkv<<<qkvgrid, 256, SMEM_G2_BYTES>>>(qxh, qxl, kxh, kxl, vx,
                                              wq, wk, wv, qh, ql, kkp, vvp); // 4

    dim3 agrid(SEQ / 128, NHEADS, BATCH);
    attn_1p<<<agrid, 256, SMEM_ATTN_BYTES>>>(qh, ql, kkp, vvp, attn, ao,
                                             linv, write_attn);            // 5 <- ncu

    dim3 ggrid(DMODEL / 128, MROWS / 128);
    gemm_out<<<ggrid, 256, SMEM_G1_BYTES>>>(ao, wo, out, b_o);             // 6

    if (write_attn) {
        dim3 ngrid(SEQ / 64, NHEADS, BATCH);
        attn_norm<<<ngrid, 256>>>(attn, linv);                             // 7
    }
}

// round 17
// speedup vs baseline: 1.0997x; 1.0997x over previous
#include <cuda_runtime.h>
#include <cuda_fp16.h>
#include <stdint.h>

#define BATCH   2
#define SEQ     2048
#define DMODEL  1024
#define NHEADS  16
#define DK      64
#define MROWS   (BATCH * SEQ)                      // 4096
#define OUT_ELEMS ((size_t)MROWS * DMODEL)

typedef __half fp16;

// ---------------- scratch (device globals) ----------------
__device__ static fp16 g_qxh[MROWS * DMODEL], g_qxl[MROWS * DMODEL];
__device__ static fp16 g_kxh[MROWS * DMODEL], g_kxl[MROWS * DMODEL];
__device__ static fp16 g_vx [MROWS * DMODEL];
__device__ static fp16 g_wq[DMODEL * DMODEL], g_wk[DMODEL * DMODEL];
__device__ static fp16 g_wv[DMODEL * DMODEL], g_wo[DMODEL * DMODEL];
__device__ static fp16 g_q [MROWS * DMODEL];                         // q single [b][h][s][d]
__device__ static fp16 g_k [MROWS * DMODEL];                         // k single [b][h][s][d]
__device__ static fp16 g_v [MROWS * DMODEL];                         // v single [b][h][d][s]
__device__ static fp16 g_ao[MROWS * DMODEL];                         // single fp16

// ---------------- helpers ----------------
__device__ __forceinline__ uint32_t sptr(const void* p) {
    return (uint32_t)__cvta_generic_to_shared(p);
}
__device__ __forceinline__ void ldsm4(uint32_t& r0, uint32_t& r1, uint32_t& r2,
                                      uint32_t& r3, uint32_t a) {
    asm volatile("ldmatrix.sync.aligned.m8n8.x4.shared.b16 {%0,%1,%2,%3},[%4];"
                 : "=r"(r0), "=r"(r1), "=r"(r2), "=r"(r3) : "r"(a));
}
__device__ __forceinline__ void mma_f16(float c[4], const uint32_t a[4],
                                        uint32_t b0, uint32_t b1) {
    asm volatile(
        "mma.sync.aligned.m16n8k16.row.col.f32.f16.f16.f32 "
        "{%0,%1,%2,%3},{%4,%5,%6,%7},{%8,%9},{%0,%1,%2,%3};"
        : "+f"(c[0]), "+f"(c[1]), "+f"(c[2]), "+f"(c[3])
        : "r"(a[0]), "r"(a[1]), "r"(a[2]), "r"(a[3]), "r"(b0), "r"(b1));
}
__device__ __forceinline__ void split2(float x, fp16& h, fp16& l) {
    h = __float2half_rn(x);
    l = __float2half_rn(x - __half2float(h));
}
__device__ __forceinline__ uint32_t pack2(fp16 a, fp16 b) {
    __half2 t; t.x = a; t.y = b;
    return *(uint32_t*)&t;
}
__device__ __forceinline__ void cpa16(void* dst, const void* src) {
    asm volatile("cp.async.cg.shared.global [%0],[%1],16;"
                 :: "r"(sptr(dst)), "l"(__cvta_generic_to_global(src)));
}
#define CP_COMMIT  asm volatile("cp.async.commit_group;")
#define CP_WAIT0   asm volatile("cp.async.wait_group 0;")
#define CP_WAIT1   asm volatile("cp.async.wait_group 1;")

// ---------------- split / convert kernels ----------------
__global__ __launch_bounds__(256)
void split_kernel(const float* __restrict__ in, fp16* __restrict__ oh,
                  fp16* __restrict__ ol, int n4)
{
    int i = blockIdx.x * blockDim.x + threadIdx.x;
    if (i >= n4) return;
    float4 v = ((const float4*)in)[i];
    fp16 h0, l0, h1, l1, h2, l2, h3, l3;
    split2(v.x, h0, l0); split2(v.y, h1, l1);
    split2(v.z, h2, l2); split2(v.w, h3, l3);
    ((uint2*)oh)[i] = make_uint2(pack2(h0, h1), pack2(h2, h3));
    ((uint2*)ol)[i] = make_uint2(pack2(l0, l1), pack2(l2, l3));
}
__global__ __launch_bounds__(256)
void cvt_kernel(const float* __restrict__ in, fp16* __restrict__ o, int n4)
{
    int i = blockIdx.x * blockDim.x + threadIdx.x;
    if (i >= n4) return;
    float4 v = ((const float4*)in)[i];
    ((uint2*)o)[i] = make_uint2(pack2(__float2half_rn(v.x), __float2half_rn(v.y)),
                                pack2(__float2half_rn(v.z), __float2half_rn(v.w)));
}
__global__ __launch_bounds__(256)
void cvt4_kernel(const float* __restrict__ w0, const float* __restrict__ w1,
                 const float* __restrict__ w2, const float* __restrict__ w3,
                 fp16* __restrict__ o0, fp16* __restrict__ o1,
                 fp16* __restrict__ o2, fp16* __restrict__ o3, int n4)
{
    int i = blockIdx.x * blockDim.x + threadIdx.x;
    if (i >= n4) return;
    int z = blockIdx.y;
    const float* in = (z == 0) ? w0 : (z == 1) ? w1 : (z == 2) ? w2 : w3;
    fp16* o = (z == 0) ? o0 : (z == 1) ? o1 : (z == 2) ? o2 : o3;
    float4 v = ((const float4*)in)[i];
    ((uint2*)o)[i] = make_uint2(pack2(__float2half_rn(v.x), __float2half_rn(v.y)),
                                pack2(__float2half_rn(v.z), __float2half_rn(v.w)));
}

// ---------------------------------------------------------------------------
// GEMM mainloops: 128x128x32, 8 warps (2x4), 3-stage cp.async pipeline.
// ---------------------------------------------------------------------------
#define G_LDS 40
#define G_TILE (128 * G_LDS)
#define SMEM_G2_BYTES (9 * G_TILE * 2)     // 92160
#define SMEM_G1_BYTES (6 * G_TILE * 2)     // 61440

#define GEMM_WAIT(kk, NK)                                                    \
    if ((kk) + 1 < (NK)) { CP_WAIT1; } else { CP_WAIT0; }                    \
    __syncthreads();

#define GEMM_MAINLOOP2(Ah, Al, Bw)                                           \
    float acc[4][4][4];                                                      \
    _Pragma("unroll")                                                        \
    for (int i = 0; i < 4; ++i)                                              \
        _Pragma("unroll")                                                    \
        for (int j = 0; j < 4; ++j)                                          \
            _Pragma("unroll")                                                \
            for (int e = 0; e < 4; ++e) acc[i][j][e] = 0.f;                  \
    auto issue = [&](int kk) {                                               \
        fp16* d = smg + (kk % 3) * 3 * G_TILE;                               \
        const fp16* srcs[3] = {                                              \
            Ah + (size_t)m0 * DMODEL + kk * 32,                              \
            Al + (size_t)m0 * DMODEL + kk * 32,                              \
            Bw + (size_t)n0 * DMODEL + kk * 32};                             \
        const int r = t >> 2, o = (t & 3) * 8;                               \
        _Pragma("unroll")                                                    \
        for (int tl = 0; tl < 3; ++tl) {                                     \
            cpa16(d + tl * G_TILE + r * G_LDS + o,                           \
                  srcs[tl] + (size_t)r * DMODEL + o);                        \
            cpa16(d + tl * G_TILE + (r + 64) * G_LDS + o,                    \
                  srcs[tl] + (size_t)(r + 64) * DMODEL + o);                 \
        }                                                                    \
    };                                                                       \
    const int NK = DMODEL / 32;                                              \
    issue(0); CP_COMMIT;                                                     \
    issue(1); CP_COMMIT;                                                     \
    for (int kk = 0; kk < NK; ++kk) {                                        \
        GEMM_WAIT(kk, NK)                                                    \
        if (kk + 2 < NK) { issue(kk + 2); CP_COMMIT; }                       \
        const fp16* sAh = smg + (kk % 3) * 3 * G_TILE;                       \
        const fp16* sAl = sAh + G_TILE;                                      \
        const fp16* sB  = sAl + G_TILE;                                      \
        _Pragma("unroll")                                                    \
        for (int k16 = 0; k16 < 32; k16 += 16) {                             \
            uint32_t ah[4][4], al[4][4], bh[4][2];                           \
            _Pragma("unroll")                                                \
            for (int mt = 0; mt < 4; ++mt) {                                 \
                int row = wm * 64 + mt * 16 + lr + 8 * (lm & 1);             \
                int col = k16 + 8 * (lm >> 1);                               \
                ldsm4(ah[mt][0], ah[mt][1], ah[mt][2], ah[mt][3],            \
                      sptr(&sAh[row * G_LDS + col]));                        \
                ldsm4(al[mt][0], al[mt][1], al[mt][2], al[mt][3],            \
                      sptr(&sAl[row * G_LDS + col]));                        \
            }                                                                \
            _Pragma("unroll")                                                \
            for (int g = 0; g < 2; ++g) {                                    \
                int row = wn * 32 + g * 16 + 8 * (lm >> 1) + lr;             \
                int col = k16 + 8 * (lm & 1);                                \
                ldsm4(bh[2 * g][0], bh[2 * g][1], bh[2 * g + 1][0],          \
                      bh[2 * g + 1][1], sptr(&sB[row * G_LDS + col]));       \
            }                                                                \
            _Pragma("unroll")                                                \
            for (int mt = 0; mt < 4; ++mt)                                   \
                _Pragma("unroll")                                            \
                for (int nt = 0; nt < 4; ++nt) {                             \
                    mma_f16(acc[mt][nt], ah[mt], bh[nt][0], bh[nt][1]);      \
                    mma_f16(acc[mt][nt], al[mt], bh[nt][0], bh[nt][1]);      \
                }                                                            \
        }                                                                    \
    }

#define GEMM_MAINLOOP1(Aa, Bw)                                               \
    float acc[4][4][4];                                                      \
    _Pragma("unroll")                                                        \
    for (int i = 0; i < 4; ++i)                                              \
        _Pragma("unroll")                                                    \
        for (int j = 0; j < 4; ++j)                                          \
            _Pragma("unroll")                                                \
            for (int e = 0; e < 4; ++e) acc[i][j][e] = 0.f;                  \
    auto issue = [&](int kk) {                                               \
        fp16* d = smg + (kk % 3) * 2 * G_TILE;                               \
        const fp16* srcs[2] = {                                              \
            Aa + (size_t)m0 * DMODEL + kk * 32,                              \
            Bw + (size_t)n0 * DMODEL + kk * 32};                             \
        const int r = t >> 2, o = (t & 3) * 8;                               \
        _Pragma("unroll")                                                    \
        for (int tl = 0; tl < 2; ++tl) {                                     \
            cpa16(d + tl * G_TILE + r * G_LDS + o,                           \
                  srcs[tl] + (size_t)r * DMODEL + o);                        \
            cpa16(d + tl * G_TILE + (r + 64) * G_LDS + o,                    \
                  srcs[tl] + (size_t)(r + 64) * DMODEL + o);                 \
        }                                                                    \
    };                                                                       \
    const int NK = DMODEL / 32;                                              \
    issue(0); CP_COMMIT;                                                     \
    issue(1); CP_COMMIT;                                                     \
    for (int kk = 0; kk < NK; ++kk) {                                        \
        GEMM_WAIT(kk, NK)                                                    \
        if (kk + 2 < NK) { issue(kk + 2); CP_COMMIT; }                       \
        const fp16* sA = smg + (kk % 3) * 2 * G_TILE;                        \
        const fp16* sB = sA + G_TILE;                                        \
        _Pragma("unroll")                                                    \
        for (int k16 = 0; k16 < 32; k16 += 16) {                             \
            uint32_t ah[4][4], bh[4][2];                                     \
            _Pragma("unroll")                                                \
            for (int mt = 0; mt < 4; ++mt) {                                 \
                int row = wm * 64 + mt * 16 + lr + 8 * (lm & 1);             \
                int col = k16 + 8 * (lm >> 1);                               \
                ldsm4(ah[mt][0], ah[mt][1], ah[mt][2], ah[mt][3],            \
                      sptr(&sA[row * G_LDS + col]));                         \
            }                                                                \
            _Pragma("unroll")                                                \
            for (int g = 0; g < 2; ++g) {                                    \
                int row = wn * 32 + g * 16 + 8 * (lm >> 1) + lr;             \
                int col = k16 + 8 * (lm & 1);                                \
                ldsm4(bh[2 * g][0], bh[2 * g][1], bh[2 * g + 1][0],          \
                      bh[2 * g + 1][1], sptr(&sB[row * G_LDS + col]));       \
            }                                                                \
            _Pragma("unroll")                                                \
            for (int mt = 0; mt < 4; ++mt)                                   \
                _Pragma("unroll")                                            \
                for (int nt = 0; nt < 4; ++nt)                               \
                    mma_f16(acc[mt][nt], ah[mt], bh[nt][0], bh[nt][1]);      \
        }                                                                    \
    }

// Fused QKV projection: z in {0:Q, 1:K} split-A -> single out; 2:V single-A
// transposed single out.
__global__ __launch_bounds__(256)
void gemm_qkv(const fp16* __restrict__ qxh, const fp16* __restrict__ qxl,
              const fp16* __restrict__ kxh, const fp16* __restrict__ kxl,
              const fp16* __restrict__ vx,
              const fp16* __restrict__ wq, const fp16* __restrict__ wk,
              const fp16* __restrict__ wv,
              fp16* __restrict__ qq, fp16* __restrict__ kkp,
              fp16* __restrict__ vvp)
{
    extern __shared__ fp16 smg[];
    const int t = threadIdx.x;
    const int m0 = blockIdx.y * 128, n0 = blockIdx.x * 128;
    const int z = blockIdx.z;
    const int w = t >> 5, lane = t & 31;
    const int wm = w >> 2, wn = w & 3;
    const int lm = lane >> 3, lr = lane & 7;
    const int cr = lane >> 2, cc = lane & 3;

    if (z == 2) {
        GEMM_MAINLOOP1(vx, wv)
#pragma unroll
        for (int mt = 0; mt < 4; ++mt)
#pragma unroll
            for (int nt = 0; nt < 4; ++nt)
#pragma unroll
                for (int half = 0; half < 2; ++half) {
                    int gm = m0 + wm * 64 + mt * 16 + cr + 8 * half;
                    int gn = n0 + wn * 32 + nt * 8 + 2 * cc;
                    int b = gm >> 11, s = gm & 2047, h = gn >> 6, d = gn & 63;
                    size_t idx = (((size_t)(b * NHEADS + h) * DK) + d) * SEQ + s;
                    vvp[idx]       = __float2half_rn(acc[mt][nt][2 * half + 0]);
                    vvp[idx + SEQ] = __float2half_rn(acc[mt][nt][2 * half + 1]);
                }
    } else {
        const fp16* Ah = (z == 0) ? qxh : kxh;
        const fp16* Al = (z == 0) ? qxl : kxl;
        const fp16* Bw = (z == 0) ? wq  : wk;
        fp16* dst = (z == 0) ? qq : kkp;
        GEMM_MAINLOOP2(Ah, Al, Bw)
#pragma unroll
        for (int mt = 0; mt < 4; ++mt)
#pragma unroll
            for (int nt = 0; nt < 4; ++nt)
#pragma unroll
                for (int half = 0; half < 2; ++half) {
                    int gm = m0 + wm * 64 + mt * 16 + cr + 8 * half;
                    int gn = n0 + wn * 32 + nt * 8 + 2 * cc;
                    int b = gm >> 11, s = gm & 2047, h = gn >> 6, d = gn & 63;
                    size_t idx = (((size_t)(b * NHEADS + h) * SEQ) + s) * DK + d;
                    *(uint32_t*)(dst + idx) =
                        pack2(__float2half_rn(acc[mt][nt][2 * half + 0]),
                              __float2half_rn(acc[mt][nt][2 * half + 1]));
                }
    }
}

// Output projection: single-A x single-B, fp32 + bias
__global__ __launch_bounds__(256)
void gemm_out(const fp16* __restrict__ ao, const fp16* __restrict__ wo,
              float* __restrict__ Cout, const float* __restrict__ bias)
{
    extern __shared__ fp16 smg[];
    const int t = threadIdx.x;
    const int m0 = blockIdx.y * 128, n0 = blockIdx.x * 128;
    const int w = t >> 5, lane = t & 31;
    const int wm = w >> 2, wn = w & 3;
    const int lm = lane >> 3, lr = lane & 7;
    const int cr = lane >> 2, cc = lane & 3;

    GEMM_MAINLOOP1(ao, wo)

#pragma unroll
    for (int mt = 0; mt < 4; ++mt)
#pragma unroll
        for (int nt = 0; nt < 4; ++nt)
#pragma unroll
            for (int half = 0; half < 2; ++half) {
                int gm = m0 + wm * 64 + mt * 16 + cr + 8 * half;
                int gn = n0 + wn * 32 + nt * 8 + 2 * cc;
                *(float2*)(Cout + (size_t)gm * DMODEL + gn) =
                    make_float2(acc[mt][nt][2 * half + 0] + bias[gn],
                                acc[mt][nt][2 * half + 1] + bias[gn + 1]);
            }
}

// ---------------------------------------------------------------------------
// Single-pass attention, 128-row Q tiles, all-single fp16 operands,
// fused in-kernel normalization sweep over the CTA's attn rows.
// ---------------------------------------------------------------------------
#define A_LDS 72
#define SMEM_ATTN_BYTES ((128 + 4 * 64) * A_LDS * 2)    // 55296

__global__ __launch_bounds__(256, 2)
void attn_1p(const fp16* __restrict__ qq_g, const fp16* __restrict__ kk_g,
             const fp16* __restrict__ vv_g, float* __restrict__ attn,
             fp16* __restrict__ ao, int write_attn)
{
    extern __shared__ fp16 sma[];
    fp16* Qs = sma;
    fp16* KB[2] = {sma + 128 * A_LDS, sma + 192 * A_LDS};
    fp16* VB[2] = {sma + 256 * A_LDS, sma + 320 * A_LDS};

    const int qt = (int)gridDim.x - 1 - (int)blockIdx.x;   // heavy first
    const int h = blockIdx.y, b = blockIdx.z;
    const int q0 = qt * 128;
    const int t = threadIdx.x, wm = t >> 5, lane = t & 31;
    const int lm = lane >> 3, lr = lane & 7;
    const int cr = lane >> 2, cc = lane & 3;
    const float scale = 0.125f;

    const size_t bh = (size_t)(b * NHEADS + h);
    const fp16* qb = qq_g + bh * SEQ * DK;
    const fp16* kb = kk_g + bh * SEQ * DK;
    const fp16* vb = vv_g + bh * DK * SEQ;

    auto cpa_kv = [&](fp16* dst, const fp16* src, int rstride) {
        const int r = t >> 2, o = (t & 3) * 16;
        cpa16(dst + r * A_LDS + o,     src + (size_t)r * rstride + o);
        cpa16(dst + r * A_LDS + o + 8, src + (size_t)r * rstride + o + 8);
    };
    auto cpa_q = [&](fp16* dst, const fp16* src) {
        const int r = t >> 1, o = (t & 1) * 32;
#pragma unroll
        for (int u = 0; u < 32; u += 8)
            cpa16(dst + r * A_LDS + o + u, src + (size_t)r * DK + o + u);
    };

    cpa_q(Qs, qb + (size_t)q0 * DK);
    cpa_kv(KB[0], kb, DK);
    cpa_kv(VB[0], vb, SEQ);
    CP_COMMIT;

    const int n_kt = 2 * qt + 2;
    float* attn_base = write_attn ? attn + (bh * SEQ + q0) * SEQ : (float*)0;
    if (write_attn) {   // zero fully-masked region j >= q0+128
        const int zr = t >> 1, zc = (t & 1) * 32;
        float4 z4 = make_float4(0.f, 0.f, 0.f, 0.f);
        for (int kt = n_kt; kt < SEQ / 64; ++kt) {
            float* dst = attn_base + (size_t)zr * SEQ + kt * 64 + zc;
#pragma unroll
            for (int u = 0; u < 32; u += 4) *(float4*)(dst + u) = z4;
        }
    }

    float o[8][4];
#pragma unroll
    for (int nt = 0; nt < 8; ++nt)
#pragma unroll
        for (int e = 0; e < 4; ++e) o[nt][e] = 0.f;
    float lp0 = 0.f, lp1 = 0.f;

    for (int kt = 0; kt < n_kt; ++kt) {
        CP_WAIT0;
        __syncthreads();
        if (kt + 1 < n_kt) {
            cpa_kv(KB[(kt + 1) & 1], kb + (size_t)(kt + 1) * 64 * DK, DK);
            cpa_kv(VB[(kt + 1) & 1], vb + (kt + 1) * 64, SEQ);
            CP_COMMIT;
        }
        const int k0 = kt * 64, buf = kt & 1;

        // ---- QK^T (single-fp16 Q) ----
        float s[8][4];
#pragma unroll
        for (int nt = 0; nt < 8; ++nt)
#pragma unroll
            for (int e = 0; e < 4; ++e) s[nt][e] = 0.f;
#pragma unroll
        for (int kc = 0; kc < 4; ++kc) {
            uint32_t af[4];
            {
                int row = wm * 16 + lr + 8 * (lm & 1);
                int col = kc * 16 + 8 * (lm >> 1);
                ldsm4(af[0], af[1], af[2], af[3], sptr(&Qs[row * A_LDS + col]));
            }
#pragma unroll
            for (int g = 0; g < 4; ++g) {
                int row = g * 16 + 8 * (lm >> 1) + lr;
                int col = kc * 16 + 8 * (lm & 1);
                uint32_t b0, b1, b2, b3;
                ldsm4(b0, b1, b2, b3, sptr(&KB[buf][row * A_LDS + col]));
                mma_f16(s[2 * g],     af, b0, b1);
                mma_f16(s[2 * g + 1], af, b2, b3);
            }
        }

        // ---- p = exp(s/8) (unnormalized), write attn, accumulate l ----
        uint32_t pp[4][4];
#pragma unroll
        for (int nt = 0; nt < 8; ++nt) {
#pragma unroll
            for (int half = 0; half < 2; ++half) {
                int i = wm * 16 + cr + 8 * half;
                int j = nt * 8 + 2 * cc;
                float p0 = 0.f, p1 = 0.f;
                if (k0 + j     <= q0 + i) p0 = __expf(s[nt][2 * half]     * scale);
                if (k0 + j + 1 <= q0 + i) p1 = __expf(s[nt][2 * half + 1] * scale);
                if (half) lp1 += p0 + p1; else lp0 += p0 + p1;
                if (write_attn)
                    *(float2*)(attn_base + (size_t)i * SEQ + k0 + j) = make_float2(p0, p1);
                pp[nt >> 1][(nt & 1) * 2 + half] =
                    pack2(__float2half_rn(p0), __float2half_rn(p1));
            }
        }

        // ---- O += P @ V ----
#pragma unroll
        for (int kc = 0; kc < 4; ++kc) {
#pragma unroll
            for (int g = 0; g < 4; ++g) {
                int row = g * 16 + 8 * (lm >> 1) + lr;
                int col = kc * 16 + 8 * (lm & 1);
                uint32_t b0, b1, b2, b3;
                ldsm4(b0, b1, b2, b3, sptr(&VB[buf][row * A_LDS + col]));
                mma_f16(o[2 * g],     pp[kc], b0, b1);
                mma_f16(o[2 * g + 1], pp[kc], b2, b3);
            }
        }
    }

    // ---- row sums + 1/l ----
    lp0 += __shfl_xor_sync(0xffffffff, lp0, 1);
    lp0 += __shfl_xor_sync(0xffffffff, lp0, 2);
    lp1 += __shfl_xor_sync(0xffffffff, lp1, 1);
    lp1 += __shfl_xor_sync(0xffffffff, lp1, 2);
    const float li0 = 1.0f / lp0;
    const float li1 = 1.0f / lp1;

    // publish per-row 1/l in smem (Q tile dead after mainloop).
    // FIX (R14 bug): publisher is one lane per cr -> condition cc == 0 ONLY.
    float* lrow = (float*)sma;
    __syncthreads();
    if (cc == 0) {
        lrow[wm * 16 + cr]     = li0;
        lrow[wm * 16 + cr + 8] = li1;
    }

    // ---- store O (scaled) ----
#pragma unroll
    for (int nt = 0; nt < 8; ++nt)
#pragma unroll
        for (int half = 0; half < 2; ++half) {
            int i = wm * 16 + cr + 8 * half;
            int d = nt * 8 + 2 * cc;
            float li = half ? li1 : li0;
            size_t idx = (size_t)(b * SEQ + q0 + i) * DMODEL + h * DK + d;
            *(uint32_t*)(ao + idx) =
                pack2(__float2half_rn(o[nt][2 * half] * li),
                      __float2half_rn(o[nt][2 * half + 1] * li));
        }

    // ---- fused normalization sweep over this CTA's attn rows ----
    if (write_attn) {
        __syncthreads();                      // lrow + all p writes visible
        const int W = n_kt * 64;              // causal prefix width (= q0+128)
#pragma unroll 1
        for (int rg = 0; rg < 4; ++rg) {
            int r = rg * 32 + (t >> 3);
            float liw = lrow[r];
            float* row = attn_base + (size_t)r * SEQ;
            for (int c = (t & 7) * 4; c < W; c += 32) {
                float4 v = *(float4*)(row + c);
                v.x *= liw; v.y *= liw; v.z *= liw; v.w *= liw;
                *(float4*)(row + c) = v;
            }
        }
    }
}

// ---------------------------------------------------------------------------
// Launch  (attn_1p is global launch index 5 -> ncu -s 5 captures it)
// ---------------------------------------------------------------------------
extern "C" void kernel_launch(void* const* d_in, const int* in_sizes, int n_in,
                              void* d_out, int out_size)
{
    const float* Q   = (const float*)d_in[0];
    const float* K   = (const float*)d_in[1];
    const float* V   = (const float*)d_in[2];
    const float* W_q = (const float*)d_in[3];
    const float* W_k = (const float*)d_in[4];
    const float* W_v = (const float*)d_in[5];
    const float* W_o = (const float*)d_in[6];
    const float* b_o = (const float*)d_in[7];
    float* out = (float*)d_out;

    const int write_attn = ((size_t)out_size > OUT_ELEMS) ? 1 : 0;
    float* attn = write_attn ? out + OUT_ELEMS : (float*)0;

    fp16 *qxh, *qxl, *kxh, *kxl, *vx;
    fp16 *wq, *wk, *wv, *wo;
    fp16 *qq, *kkp, *vvp, *ao;
    cudaGetSymbolAddress((void**)&qxh, g_qxh); cudaGetSymbolAddress((void**)&qxl, g_qxl);
    cudaGetSymbolAddress((void**)&kxh, g_kxh); cudaGetSymbolAddress((void**)&kxl, g_kxl);
    cudaGetSymbolAddress((void**)&vx, g_vx);
    cudaGetSymbolAddress((void**)&wq, g_wq);   cudaGetSymbolAddress((void**)&wk, g_wk);
    cudaGetSymbolAddress((void**)&wv, g_wv);   cudaGetSymbolAddress((void**)&wo, g_wo);
    cudaGetSymbolAddress((void**)&qq, g_q);    cudaGetSymbolAddress((void**)&kkp, g_k);
    cudaGetSymbolAddress((void**)&vvp, g_v);   cudaGetSymbolAddress((void**)&ao, g_ao);

    cudaFuncSetAttribute(gemm_qkv, cudaFuncAttributeMaxDynamicSharedMemorySize, SMEM_G2_BYTES);
    cudaFuncSetAttribute(gemm_out, cudaFuncAttributeMaxDynamicSharedMemorySize, SMEM_G1_BYTES);
    cudaFuncSetAttribute(attn_1p,  cudaFuncAttributeMaxDynamicSharedMemorySize, SMEM_ATTN_BYTES);

    const int n4x = MROWS * DMODEL / 4;
    const int n4w = DMODEL * DMODEL / 4;

    split_kernel<<<n4x / 256, 256>>>(Q, qxh, qxl, n4x);                    // 0
    split_kernel<<<n4x / 256, 256>>>(K, kxh, kxl, n4x);                    // 1
    cvt_kernel<<<n4x / 256, 256>>>(V, vx, n4x);                            // 2
    dim3 wgrid(n4w / 256, 4);
    cvt4_kernel<<<wgrid, 256>>>(W_q, W_k, W_v, W_o, wq, wk, wv, wo, n4w);  // 3

    dim3 qkvgrid(DMODEL / 128, MROWS / 128, 3);
    gemm_qkv<<<qkvgrid, 256, SMEM_G2_BYTES>>>(qxh, qxl, kxh, kxl, vx,
                                              wq, wk, wv, qq, kkp, vvp);   // 4

    dim3 agrid(SEQ / 128, NHEADS, BATCH);
    attn_1p<<<agrid, 256, SMEM_ATTN_BYTES>>>(qq, kkp, vvp, attn, ao,
                                             write_attn);                  // 5 <- ncu

    dim3 ggrid(DMODEL / 128, MROWS / 128);
    gemm_out<<<ggrid, 256, SMEM_G1_BYTES>>>(ao, wo, out, b_o);             // 6
}